// round 7
// baseline (speedup 1.0000x reference)
#include <cuda_runtime.h>
#include <cuda_bf16.h>

// Problem constants
#define QN      4        // n_codebooks
#define KCODES  512      // codes per codebook
#define DDIM    256      // vector dim (== C)
#define HH      1024
#define WW      4
#define BB      16
#define NROWS   65536    // B*W*H
#define TILE_H  16
#define ROWS    64       // rows per CTA (TILE_H * WW)
#define CTILE   32       // codes per smem tile (shrunk for 2 CTAs/SM)
#define KK      128      // DDIM/2 (float2 pairs)
#define NCTA    1024     // BB * (HH/TILE_H)

#define IDX_OFF   (NROWS*DDIM)            // 16777216
#define LOSS_OFF  (IDX_OFF + NROWS*QN)    // 17039360

// ||c||^2 emulating XLA-GPU row-reduce: 32 strided partials (mul+add), shfl tree
__device__ float g_norms[QN*KCODES];
__device__ float g_loss_part[NCTA][QN];
__device__ int   g_done = 0;

struct SmemT {
    float2 xs2[KK][ROWS];   // residual, EXACT fp32, pair-interleaved   (64KB)
    float2 cs2[KK][CTILE];  // code tile (exact fp32)                   (32KB)
    float  cn[CTILE];       // code norms for tile
    float  r2f[ROWS];       // ||r||^2 (XLA-GPU-order emulated) at stage start
    int    cand[2][ROWS];   // top-2 candidate indices per row
    float  dc[2][ROWS];     // rescored reference-style distances
    int    sidx[ROWS];
    float  rsum[ROWS];
    int    isLast;
};
#define SMEM_BYTES (sizeof(SmemT))

// Packed dual-fp32 FMA (B300 FFMA2) — 2x fp32 throughput vs scalar FFMA.
__device__ __forceinline__ void ffma2(float2 &d, const float2 &a, const float2 &b) {
    unsigned long long dd = *reinterpret_cast<const unsigned long long*>(&d);
    asm("fma.rn.f32x2 %0, %1, %2, %3;"
        : "=l"(dd)
        : "l"(*reinterpret_cast<const unsigned long long*>(&a)),
          "l"(*reinterpret_cast<const unsigned long long*>(&b)),
          "l"(dd));
    d = *reinterpret_cast<float2*>(&dd);
}

// insert candidate (sc,gi) into sorted best-2 list; ties keep lower index
__device__ __forceinline__ void upd2(float &b0, int &i0, float &b1, int &i1,
                                     float sc, int gi) {
    if (sc < b0 || (sc == b0 && gi < i0)) {
        b1 = b0; i1 = i0; b0 = sc; i0 = gi;
    } else if (sc < b1 || (sc == b1 && gi < i1)) {
        b1 = sc; i1 = gi;
    }
}

// ---------------- code norms: XLA-GPU row-reduce emulation (FROZEN) ----------------
__global__ void rvq_norms_kernel(const float* __restrict__ cb) {
    int warp = (blockIdx.x * blockDim.x + threadIdx.x) >> 5;
    int lane = threadIdx.x & 31;
    if (warp >= QN * KCODES) return;
    const float* row = cb + (long)warp * DDIM;
    float s = 0.f;
    #pragma unroll
    for (int i = 0; i < 8; ++i) {
        float v = __ldg(&row[lane + 32 * i]);
        s = __fadd_rn(s, __fmul_rn(v, v));
    }
    #pragma unroll
    for (int off = 16; off >= 1; off >>= 1)
        s = __fadd_rn(s, __shfl_down_sync(0xffffffffu, s, off));
    if (lane == 0) g_norms[warp] = s;
}

// ---------------- main fused RVQ (now includes loss finalize) ----------------
__global__ __launch_bounds__(256, 2)
void rvq_main_kernel(const float* __restrict__ x, const float* __restrict__ cb,
                     float* __restrict__ out, int out_size) {
    extern __shared__ char smem_raw[];
    SmemT& S = *reinterpret_cast<SmemT*>(smem_raw);

    const int tid = threadIdx.x;
    const int tx = tid & 7;        // code group (4 codes each -> 32)
    const int ty = tid >> 3;       // row group  (2 rows each -> 64)
    const int cta = blockIdx.x;
    const int b  = cta >> 6;
    const int h0 = (cta & 63) * TILE_H;

    // ---- load x tile into smem (coalesced: per c, 64 contiguous floats) ----
    {
        const float4* xsrc4 = reinterpret_cast<const float4*>(x);
        #pragma unroll
        for (int t = tid; t < DDIM * 16; t += 256) {
            int c = t >> 4;
            int f4c = t & 15;
            long idx4 = ((long)(b * DDIM + c)) * HH + h0 + f4c; // float4 index
            float4 v = __ldg(&xsrc4[idx4]);
            int kk = c >> 1;
            int hi = c & 1;
            int lr0 = f4c * 4;
            reinterpret_cast<float*>(&S.xs2[kk][lr0 + 0])[hi] = v.x;
            reinterpret_cast<float*>(&S.xs2[kk][lr0 + 1])[hi] = v.y;
            reinterpret_cast<float*>(&S.xs2[kk][lr0 + 2])[hi] = v.z;
            reinterpret_cast<float*>(&S.xs2[kk][lr0 + 3])[hi] = v.w;
        }
    }
    __syncthreads();

    const bool write_idx = (out_size >= IDX_OFF + NROWS*QN);

    // ---- 4 sequential quantization stages ----
    for (int q = 0; q < QN; ++q) {
        // ||r||^2 emulating XLA-GPU row-reduce (FROZEN arithmetic)
        if (tid < ROWS) {
            float p[32];
            #pragma unroll
            for (int t = 0; t < 32; ++t) {
                float s = 0.f;
                #pragma unroll
                for (int i = 0; i < 8; ++i) {
                    int k = t + 32 * i;
                    float v = reinterpret_cast<const float*>(&S.xs2[k >> 1][tid])[k & 1];
                    s = __fadd_rn(s, __fmul_rn(v, v));
                }
                p[t] = s;
            }
            #pragma unroll
            for (int off = 16; off >= 1; off >>= 1)
                #pragma unroll
                for (int t = 0; t < 16; ++t)
                    if (t < off) p[t] = __fadd_rn(p[t], p[t + off]);
            S.r2f[tid] = p[0];
        }

        float best0[2], best1[2];
        int   idx0[2],  idx1[2];
        #pragma unroll
        for (int i = 0; i < 2; ++i) {
            best0[i] = 3.4e38f; best1[i] = 3.4e38f;
            idx0[i] = 0x7fffffff; idx1[i] = 0x7fffffff;
        }

        for (int ct = 0; ct < KCODES / CTILE; ++ct) {
            __syncthreads();  // previous tile compute done / cs2 free; r2f done (ct==0)
            // load 32 codes x 256 dims into cs2 (pair-interleaved)
            const float4* cbsrc = reinterpret_cast<const float4*>(
                cb + ((long)(q * KCODES + ct * CTILE)) * DDIM);
            #pragma unroll
            for (int t = tid; t < CTILE * 64; t += 256) {
                int j  = t >> 6;
                int f4 = t & 63;
                float4 v = __ldg(&cbsrc[j * 64 + f4]);
                int kk = f4 * 2;
                S.cs2[kk][j]     = make_float2(v.x, v.y);
                S.cs2[kk + 1][j] = make_float2(v.z, v.w);
            }
            if (tid < CTILE) S.cn[tid] = g_norms[q * KCODES + ct * CTILE + tid];
            __syncthreads();

            // 2x4 register-blocked fp32 dot products, FFMA2 inner loop (approx scan)
            float2 acc[2][4];
            #pragma unroll
            for (int i = 0; i < 2; ++i)
                #pragma unroll
                for (int j = 0; j < 4; ++j) acc[i][j] = make_float2(0.f, 0.f);

            #pragma unroll 8
            for (int kk = 0; kk < KK; ++kk) {
                float4 rv4 = *reinterpret_cast<const float4*>(&S.xs2[kk][ty * 2]);
                float4 ca  = *reinterpret_cast<const float4*>(&S.cs2[kk][tx * 4]);
                float4 cc  = *reinterpret_cast<const float4*>(&S.cs2[kk][tx * 4 + 2]);
                float2 r0 = make_float2(rv4.x, rv4.y);
                float2 r1 = make_float2(rv4.z, rv4.w);
                float2 cv[4] = { make_float2(ca.x, ca.y), make_float2(ca.z, ca.w),
                                 make_float2(cc.x, cc.y), make_float2(cc.z, cc.w) };
                #pragma unroll
                for (int j = 0; j < 4; ++j) {
                    ffma2(acc[0][j], r0, cv[j]);
                    ffma2(acc[1][j], r1, cv[j]);
                }
            }
            // approximate scores for candidate SELECTION; keep best-2 per row
            #pragma unroll
            for (int j = 0; j < 4; ++j) {
                float n2 = S.cn[tx * 4 + j];
                int gidx = ct * CTILE + tx * 4 + j;
                #pragma unroll
                for (int i = 0; i < 2; ++i) {
                    float dot = acc[i][j].x + acc[i][j].y;
                    float sc = fmaf(-2.f, dot, n2);
                    upd2(best0[i], idx0[i], best1[i], idx1[i], sc, gidx);
                }
            }
        }

        // merge best-2 lists across the 8 tx lanes sharing each row
        #pragma unroll
        for (int i = 0; i < 2; ++i) {
            #pragma unroll
            for (int off = 4; off; off >>= 1) {
                float ob0 = __shfl_xor_sync(0xffffffffu, best0[i], off);
                int   oi0 = __shfl_xor_sync(0xffffffffu, idx0[i],  off);
                float ob1 = __shfl_xor_sync(0xffffffffu, best1[i], off);
                int   oi1 = __shfl_xor_sync(0xffffffffu, idx1[i],  off);
                upd2(best0[i], idx0[i], best1[i], idx1[i], ob0, oi0);
                upd2(best0[i], idx0[i], best1[i], idx1[i], ob1, oi1);
            }
        }
        if (tx == 0) {
            #pragma unroll
            for (int i = 0; i < 2; ++i) {
                S.cand[0][ty * 2 + i] = idx0[i];
                S.cand[1][ty * 2 + i] = idx1[i];
            }
        }
        __syncthreads();

        // ---- rescore top-2 emulating cuBLAS SGEMM arithmetic (FROZEN) ----
        if (tid < 2 * ROWS) {
            int row = tid >> 1;
            int c   = tid & 1;
            int idx = S.cand[c][row];
            const float2* crow = reinterpret_cast<const float2*>(
                cb + ((long)(q * KCODES + idx)) * DDIM);
            float acc = 0.f;
            #pragma unroll 8
            for (int kk = 0; kk < KK; ++kk) {
                float2 r  = S.xs2[kk][row];
                float2 cv = __ldg(&crow[kk]);
                acc = fmaf(r.x, cv.x, acc);
                acc = fmaf(r.y, cv.y, acc);
            }
            float t = __fsub_rn(S.r2f[row], __fmul_rn(2.f, acc));
            S.dc[c][row] = __fadd_rn(t, g_norms[q * KCODES + idx]);
        }
        __syncthreads();
        if (tid < ROWS) {
            float d0 = S.dc[0][tid], d1 = S.dc[1][tid];
            int   i0 = S.cand[0][tid], i1 = S.cand[1][tid];
            int win = (d1 < d0 || (d1 == d0 && i1 < i0)) ? i1 : i0;
            S.sidx[tid] = win;
        }
        __syncthreads();  // sidx visible; all xs2 reads done before mutation

        // residual update: r -= chosen code (4 threads per row, 64 dims each)
        {
            int lr = tid & 63;
            int ks = tid >> 6;
            int idx = S.sidx[lr];
            const float4* crow = reinterpret_cast<const float4*>(
                cb + ((long)(q * KCODES + idx)) * DDIM);
            #pragma unroll
            for (int f4 = ks * 16; f4 < ks * 16 + 16; ++f4) {
                float4 v = __ldg(&crow[f4]);
                int kk = f4 * 2;
                float2 a = S.xs2[kk][lr];     a.x -= v.x; a.y -= v.y; S.xs2[kk][lr] = a;
                float2 c2 = S.xs2[kk + 1][lr]; c2.x -= v.z; c2.y -= v.w; S.xs2[kk + 1][lr] = c2;
            }
        }

        // indices output (as float)
        if (write_idx && tid < ROWS) {
            int w = tid & 3, hh = tid >> 2;
            long n = ((long)(b * WW + w)) * HH + h0 + hh;
            out[IDX_OFF + n * QN + q] = (float)S.sidx[tid];
        }
        __syncthreads();  // residual update complete

        // loss: elementwise sum ||r_{q+1}||^2 (deterministic order)
        if (tid < ROWS) {
            float s = 0.f;
            #pragma unroll 8
            for (int kk = 0; kk < KK; ++kk) {
                float2 v = S.xs2[kk][tid];
                s = fmaf(v.x, v.x, s);
                s = fmaf(v.y, v.y, s);
            }
            S.rsum[tid] = s;
        }
        __syncthreads();
        if (tid == 0) {
            float s = 0.f;
            #pragma unroll
            for (int i = 0; i < ROWS; ++i) s += S.rsum[i];
            g_loss_part[cta][q] = s;
        }
    }
    __syncthreads();

    // ---- quantized_out = x - residual_final (exact fp32) ----
    {
        int lr = tid & 63;
        int ks = tid >> 6;
        int w = lr & 3, hh = lr >> 2;
        long n = ((long)(b * WW + w)) * HH + h0 + hh;
        float4* orow = reinterpret_cast<float4*>(out + n * DDIM);
        long cbase = (((long)b * DDIM) * HH + (h0 + hh)) * WW + w;  // offset at c=0
        #pragma unroll
        for (int f4 = ks * 16; f4 < ks * 16 + 16; ++f4) {
            int c0 = f4 * 4;
            float x0 = __ldg(&x[cbase + (long)(c0 + 0) * (HH * WW)]);
            float x1 = __ldg(&x[cbase + (long)(c0 + 1) * (HH * WW)]);
            float x2 = __ldg(&x[cbase + (long)(c0 + 2) * (HH * WW)]);
            float x3 = __ldg(&x[cbase + (long)(c0 + 3) * (HH * WW)]);
            float2 r0 = S.xs2[f4 * 2][lr];
            float2 r1 = S.xs2[f4 * 2 + 1][lr];
            float4 o;
            o.x = x0 - r0.x; o.y = x1 - r0.y;
            o.z = x2 - r1.x; o.w = x3 - r1.y;
            orow[f4] = o;
        }
    }

    // ---- fused loss finalize: last CTA reduces g_loss_part (fixed order) ----
    __threadfence();
    __syncthreads();
    if (tid == 0) {
        int old = atomicAdd(&g_done, 1);
        S.isLast = (old == (int)gridDim.x - 1) ? 1 : 0;
    }
    __syncthreads();
    if (S.isLast) {
        if (out_size >= LOSS_OFF + QN && tid < 128) {
            int q = tid >> 5;
            int lane = tid & 31;
            float s = 0.f;
            for (int i = lane; i < NCTA; i += 32) s += g_loss_part[i][q];
            #pragma unroll
            for (int off = 16; off; off >>= 1)
                s += __shfl_xor_sync(0xffffffffu, s, off);
            if (lane == 0) out[LOSS_OFF + q] = s / (float)(NROWS * DDIM);
        }
        if (tid == 0) g_done = 0;   // reset for next graph replay
    }
}

extern "C" void kernel_launch(void* const* d_in, const int* in_sizes, int n_in,
                              void* d_out, int out_size) {
    const float* x  = (const float*)d_in[0];   // encoded_x [16,256,1024,4]
    const float* cb = (const float*)d_in[1];   // codebooks [4,512,256]
    float* out = (float*)d_out;

    cudaFuncSetAttribute(rvq_main_kernel,
                         cudaFuncAttributeMaxDynamicSharedMemorySize,
                         (int)SMEM_BYTES);

    rvq_norms_kernel<<<(QN*KCODES*32 + 255)/256, 256>>>(cb);
    rvq_main_kernel<<<NCTA, 256, SMEM_BYTES>>>(x, cb, out, out_size);
}

// round 8
// speedup vs baseline: 3.3708x; 3.3708x over previous
#include <cuda_runtime.h>
#include <cuda_bf16.h>

// Problem constants
#define QN      4        // n_codebooks
#define KCODES  512      // codes per codebook
#define DDIM    256      // vector dim (== C)
#define HH      1024
#define WW      4
#define BB      16
#define NROWS   65536    // B*W*H
#define TILE_H  32
#define ROWS    128      // rows per CTA (TILE_H * WW)
#define CTILE   64       // codes per smem tile
#define KK      128      // DDIM/2 (float2 pairs)
#define NCTA    512      // BB * (HH/TILE_H)
#define NTHR    512
#define CROW    132      // padded floats per cs2f row (CTILE*2 + 4)

#define IDX_OFF   (NROWS*DDIM)            // 16777216
#define LOSS_OFF  (IDX_OFF + NROWS*QN)    // 17039360

__device__ float g_norms[QN*KCODES];
__device__ float g_loss_part[NCTA][QN];
__device__ int   g_done = 0;

struct SmemT {
    float2 xs2[KK][ROWS];     // residual, EXACT fp32, pair-interleaved (128KB)
    float  cs2f[KK * CROW];   // code tile, swizzled chunks, padded rows (66KB)
    float  cn[CTILE];
    float  r2f[ROWS];
    int    cand[2][ROWS];
    float  dc[2][ROWS];
    int    sidx[ROWS];
    float  rsum[ROWS];
    int    isLast;
};
#define SMEM_BYTES (sizeof(SmemT))

// Packed dual-fp32 FMA (B300 FFMA2)
__device__ __forceinline__ void ffma2(float2 &d, const float2 &a, const float2 &b) {
    unsigned long long dd = *reinterpret_cast<const unsigned long long*>(&d);
    asm("fma.rn.f32x2 %0, %1, %2, %3;"
        : "=l"(dd)
        : "l"(*reinterpret_cast<const unsigned long long*>(&a)),
          "l"(*reinterpret_cast<const unsigned long long*>(&b)),
          "l"(dd));
    d = *reinterpret_cast<float2*>(&dd);
}

__device__ __forceinline__ void upd2(float &b0, int &i0, float &b1, int &i1,
                                     float sc, int gi) {
    if (sc < b0 || (sc == b0 && gi < i0)) {
        b1 = b0; i1 = i0; b0 = sc; i0 = gi;
    } else if (sc < b1 || (sc == b1 && gi < i1)) {
        b1 = sc; i1 = gi;
    }
}

// ---------------- code norms: XLA-GPU row-reduce emulation (FROZEN) ----------------
__global__ void rvq_norms_kernel(const float* __restrict__ cb) {
    int warp = (blockIdx.x * blockDim.x + threadIdx.x) >> 5;
    int lane = threadIdx.x & 31;
    if (warp >= QN * KCODES) return;
    const float* row = cb + (long)warp * DDIM;
    float s = 0.f;
    #pragma unroll
    for (int i = 0; i < 8; ++i) {
        float v = __ldg(&row[lane + 32 * i]);
        s = __fadd_rn(s, __fmul_rn(v, v));
    }
    #pragma unroll
    for (int off = 16; off >= 1; off >>= 1)
        s = __fadd_rn(s, __shfl_down_sync(0xffffffffu, s, off));
    if (lane == 0) g_norms[warp] = s;
}

// ---------------- main fused RVQ ----------------
__global__ __launch_bounds__(NTHR, 1)
void rvq_main_kernel(const float* __restrict__ x, const float* __restrict__ cb,
                     float* __restrict__ out, int out_size) {
    extern __shared__ char smem_raw[];
    SmemT& S = *reinterpret_cast<SmemT*>(smem_raw);

    const int tid = threadIdx.x;
    const int tx = tid & 15;       // 16 code groups (4 codes each)
    const int ty = tid >> 4;       // 32 row groups  (4 rows each)
    const int wid = tid >> 5;      // 16 warps
    const int lane = tid & 31;
    const int cta = blockIdx.x;
    const int b  = cta >> 5;
    const int h0 = (cta & 31) * TILE_H;

    // swizzled float offsets for the two 16B code chunks this thread reads
    const int caoff = ((2 * tx)     ^ ((tx >> 2) & 1)) * 4;
    const int ccoff = ((2 * tx + 1) ^ ((tx >> 2) & 1)) * 4;
    // store-side indices (constant per thread)
    const int sj_base = tid >> 6;        // code low bits (grows by 8 per u)
    const int sf4     = tid & 63;        // dim float4 index

    // ---- load x tile into smem (coalesced: per c, contiguous h*w floats) ----
    {
        const float4* xsrc4 = reinterpret_cast<const float4*>(x);
        for (int t = tid; t < DDIM * (TILE_H / 1); t += NTHR) {
            // t over DDIM*32 entries: c = t>>5, f4c = t&31
            int c = t >> 5;
            int f4c = t & 31;
            long idx4 = ((long)(b * DDIM + c)) * HH + h0 + f4c;
            float4 v = __ldg(&xsrc4[idx4]);
            int kk = c >> 1;
            int hi = c & 1;
            int lr0 = f4c * 4;
            reinterpret_cast<float*>(&S.xs2[kk][lr0 + 0])[hi] = v.x;
            reinterpret_cast<float*>(&S.xs2[kk][lr0 + 1])[hi] = v.y;
            reinterpret_cast<float*>(&S.xs2[kk][lr0 + 2])[hi] = v.z;
            reinterpret_cast<float*>(&S.xs2[kk][lr0 + 3])[hi] = v.w;
        }
    }
    __syncthreads();

    const bool write_idx = (out_size >= IDX_OFF + NROWS*QN);

    for (int q = 0; q < QN; ++q) {
        // ---- ||r||^2, XLA-GPU order (FROZEN), warp-per-row ----
        #pragma unroll
        for (int pass = 0; pass < ROWS / 16; ++pass) {
            int row = pass * 16 + wid;
            float s = 0.f;
            #pragma unroll
            for (int i = 0; i < 8; ++i) {
                int k = lane + 32 * i;
                float v = reinterpret_cast<const float*>(&S.xs2[k >> 1][row])[k & 1];
                s = __fadd_rn(s, __fmul_rn(v, v));
            }
            #pragma unroll
            for (int off = 16; off >= 1; off >>= 1)
                s = __fadd_rn(s, __shfl_down_sync(0xffffffffu, s, off));
            if (lane == 0) S.r2f[row] = s;
        }

        float best0[4], best1[4];
        int   idx0[4],  idx1[4];
        #pragma unroll
        for (int i = 0; i < 4; ++i) {
            best0[i] = 3.4e38f; best1[i] = 3.4e38f;
            idx0[i] = 0x7fffffff; idx1[i] = 0x7fffffff;
        }

        // ---- load tile 0 (swizzled) ----
        {
            const float4* cbsrc = reinterpret_cast<const float4*>(
                cb + ((long)(q * KCODES)) * DDIM);
            #pragma unroll
            for (int u = 0; u < 8; ++u) {
                int j = sj_base + u * 8;
                float4 v = __ldg(&cbsrc[j * 64 + sf4]);
                int sc = (j >> 1) ^ ((j >> 4) & 1);
                int off = sc * 4 + (j & 1) * 2;
                *reinterpret_cast<float2*>(&S.cs2f[(2*sf4)   * CROW + off]) = make_float2(v.x, v.y);
                *reinterpret_cast<float2*>(&S.cs2f[(2*sf4+1) * CROW + off]) = make_float2(v.z, v.w);
            }
            if (tid < CTILE) S.cn[tid] = g_norms[q * KCODES + tid];
        }
        __syncthreads();

        for (int ct = 0; ct < KCODES / CTILE; ++ct) {
            // prefetch next tile into registers
            float4 st[8];
            if (ct < KCODES / CTILE - 1) {
                const float4* cbsrc = reinterpret_cast<const float4*>(
                    cb + ((long)(q * KCODES + (ct + 1) * CTILE)) * DDIM);
                #pragma unroll
                for (int u = 0; u < 8; ++u)
                    st[u] = __ldg(&cbsrc[(sj_base + u * 8) * 64 + sf4]);
            }

            // 4x4 register-blocked dot products, FFMA2, swizzled conflict-free loads
            float2 acc[4][4];
            #pragma unroll
            for (int i = 0; i < 4; ++i)
                #pragma unroll
                for (int j = 0; j < 4; ++j) acc[i][j] = make_float2(0.f, 0.f);

            #pragma unroll 4
            for (int kk = 0; kk < KK; ++kk) {
                const float* crow = &S.cs2f[kk * CROW];
                float4 ca = *reinterpret_cast<const float4*>(crow + caoff);
                float4 cc = *reinterpret_cast<const float4*>(crow + ccoff);
                float4 ra = *reinterpret_cast<const float4*>(&S.xs2[kk][ty * 4]);
                float4 rb = *reinterpret_cast<const float4*>(&S.xs2[kk][ty * 4 + 2]);
                float2 rv[4] = { make_float2(ra.x, ra.y), make_float2(ra.z, ra.w),
                                 make_float2(rb.x, rb.y), make_float2(rb.z, rb.w) };
                float2 cv[4] = { make_float2(ca.x, ca.y), make_float2(ca.z, ca.w),
                                 make_float2(cc.x, cc.y), make_float2(cc.z, cc.w) };
                #pragma unroll
                for (int i = 0; i < 4; ++i)
                    #pragma unroll
                    for (int j = 0; j < 4; ++j)
                        ffma2(acc[i][j], rv[i], cv[j]);
            }
            #pragma unroll
            for (int j = 0; j < 4; ++j) {
                float n2 = S.cn[tx * 4 + j];
                int gidx = ct * CTILE + tx * 4 + j;
                #pragma unroll
                for (int i = 0; i < 4; ++i) {
                    float dot = acc[i][j].x + acc[i][j].y;
                    float sc = fmaf(-2.f, dot, n2);
                    upd2(best0[i], idx0[i], best1[i], idx1[i], sc, gidx);
                }
            }
            __syncthreads();   // all reads of cs2f/cn done
            if (ct < KCODES / CTILE - 1) {
                #pragma unroll
                for (int u = 0; u < 8; ++u) {
                    int j = sj_base + u * 8;
                    int sc = (j >> 1) ^ ((j >> 4) & 1);
                    int off = sc * 4 + (j & 1) * 2;
                    float4 v = st[u];
                    *reinterpret_cast<float2*>(&S.cs2f[(2*sf4)   * CROW + off]) = make_float2(v.x, v.y);
                    *reinterpret_cast<float2*>(&S.cs2f[(2*sf4+1) * CROW + off]) = make_float2(v.z, v.w);
                }
                if (tid < CTILE)
                    S.cn[tid] = g_norms[q * KCODES + (ct + 1) * CTILE + tid];
                __syncthreads();
            }
        }

        // merge best-2 across the 16 tx lanes sharing each row group
        #pragma unroll
        for (int i = 0; i < 4; ++i) {
            #pragma unroll
            for (int off = 8; off; off >>= 1) {
                float ob0 = __shfl_xor_sync(0xffffffffu, best0[i], off);
                int   oi0 = __shfl_xor_sync(0xffffffffu, idx0[i],  off);
                float ob1 = __shfl_xor_sync(0xffffffffu, best1[i], off);
                int   oi1 = __shfl_xor_sync(0xffffffffu, idx1[i],  off);
                upd2(best0[i], idx0[i], best1[i], idx1[i], ob0, oi0);
                upd2(best0[i], idx0[i], best1[i], idx1[i], ob1, oi1);
            }
        }
        if (tx == 0) {
            #pragma unroll
            for (int i = 0; i < 4; ++i) {
                S.cand[0][ty * 4 + i] = idx0[i];
                S.cand[1][ty * 4 + i] = idx1[i];
            }
        }
        __syncthreads();

        // ---- rescore top-2, cuBLAS-SGEMM arithmetic (FROZEN) ----
        if (tid < 2 * ROWS) {
            int row = tid >> 1;
            int c   = tid & 1;
            int idx = S.cand[c][row];
            const float2* crow = reinterpret_cast<const float2*>(
                cb + ((long)(q * KCODES + idx)) * DDIM);
            float acc = 0.f;
            #pragma unroll 8
            for (int kk = 0; kk < KK; ++kk) {
                float2 r  = S.xs2[kk][row];
                float2 cv = __ldg(&crow[kk]);
                acc = fmaf(r.x, cv.x, acc);
                acc = fmaf(r.y, cv.y, acc);
            }
            float t = __fsub_rn(S.r2f[row], __fmul_rn(2.f, acc));
            S.dc[c][row] = __fadd_rn(t, g_norms[q * KCODES + idx]);
        }
        __syncthreads();
        if (tid < ROWS) {
            float d0 = S.dc[0][tid], d1 = S.dc[1][tid];
            int   i0 = S.cand[0][tid], i1 = S.cand[1][tid];
            int win = (d1 < d0 || (d1 == d0 && i1 < i0)) ? i1 : i0;
            S.sidx[tid] = win;
        }
        __syncthreads();

        // residual update: r -= chosen code (4 threads per row, 64 dims each)
        {
            int lr = tid & (ROWS - 1);
            int ks = tid >> 7;           // 0..3
            int idx = S.sidx[lr];
            const float4* crow = reinterpret_cast<const float4*>(
                cb + ((long)(q * KCODES + idx)) * DDIM);
            #pragma unroll
            for (int f4 = ks * 16; f4 < ks * 16 + 16; ++f4) {
                float4 v = __ldg(&crow[f4]);
                int kk = f4 * 2;
                float2 a = S.xs2[kk][lr];     a.x -= v.x; a.y -= v.y; S.xs2[kk][lr] = a;
                float2 c2 = S.xs2[kk + 1][lr]; c2.x -= v.z; c2.y -= v.w; S.xs2[kk + 1][lr] = c2;
            }
        }

        if (write_idx && tid < ROWS) {
            int w = tid & 3, hh = tid >> 2;
            long n = ((long)(b * WW + w)) * HH + h0 + hh;
            out[IDX_OFF + n * QN + q] = (float)S.sidx[tid];
        }
        __syncthreads();

        // loss: elementwise sum ||r_{q+1}||^2 (deterministic order)
        if (tid < ROWS) {
            float s = 0.f;
            #pragma unroll 8
            for (int kk = 0; kk < KK; ++kk) {
                float2 v = S.xs2[kk][tid];
                s = fmaf(v.x, v.x, s);
                s = fmaf(v.y, v.y, s);
            }
            S.rsum[tid] = s;
        }
        __syncthreads();
        if (tid == 0) {
            float s = 0.f;
            #pragma unroll
            for (int i = 0; i < ROWS; ++i) s += S.rsum[i];
            g_loss_part[cta][q] = s;
        }
    }
    __syncthreads();

    // ---- quantized_out = x - residual_final (exact fp32) ----
    {
        int lr = tid & (ROWS - 1);
        int ks = tid >> 7;
        int w = lr & 3, hh = lr >> 2;
        long n = ((long)(b * WW + w)) * HH + h0 + hh;
        float4* orow = reinterpret_cast<float4*>(out + n * DDIM);
        long cbase = (((long)b * DDIM) * HH + (h0 + hh)) * WW + w;
        #pragma unroll
        for (int f4 = ks * 16; f4 < ks * 16 + 16; ++f4) {
            int c0 = f4 * 4;
            float x0 = __ldg(&x[cbase + (long)(c0 + 0) * (HH * WW)]);
            float x1 = __ldg(&x[cbase + (long)(c0 + 1) * (HH * WW)]);
            float x2 = __ldg(&x[cbase + (long)(c0 + 2) * (HH * WW)]);
            float x3 = __ldg(&x[cbase + (long)(c0 + 3) * (HH * WW)]);
            float2 r0 = S.xs2[f4 * 2][lr];
            float2 r1 = S.xs2[f4 * 2 + 1][lr];
            float4 o;
            o.x = x0 - r0.x; o.y = x1 - r0.y;
            o.z = x2 - r1.x; o.w = x3 - r1.y;
            orow[f4] = o;
        }
    }

    // ---- fused loss finalize: last CTA reduces g_loss_part (fixed order) ----
    __threadfence();
    __syncthreads();
    if (tid == 0) {
        int old = atomicAdd(&g_done, 1);
        S.isLast = (old == (int)gridDim.x - 1) ? 1 : 0;
    }
    __syncthreads();
    if (S.isLast) {
        if (out_size >= LOSS_OFF + QN && tid < 128) {
            int q = tid >> 5;
            int ln = tid & 31;
            float s = 0.f;
            for (int i = ln; i < NCTA; i += 32) s += g_loss_part[i][q];
            #pragma unroll
            for (int off = 16; off; off >>= 1)
                s += __shfl_xor_sync(0xffffffffu, s, off);
            if (ln == 0) out[LOSS_OFF + q] = s / (float)(NROWS * DDIM);
        }
        if (tid == 0) g_done = 0;   // reset for next graph replay
    }
}

extern "C" void kernel_launch(void* const* d_in, const int* in_sizes, int n_in,
                              void* d_out, int out_size) {
    const float* x  = (const float*)d_in[0];   // encoded_x [16,256,1024,4]
    const float* cb = (const float*)d_in[1];   // codebooks [4,512,256]
    float* out = (float*)d_out;

    cudaFuncSetAttribute(rvq_main_kernel,
                         cudaFuncAttributeMaxDynamicSharedMemorySize,
                         (int)SMEM_BYTES);

    rvq_norms_kernel<<<(QN*KCODES*32 + 255)/256, 256>>>(cb);
    rvq_main_kernel<<<NCTA, NTHR, SMEM_BYTES>>>(x, cb, out, out_size);
}

// round 10
// speedup vs baseline: 3.8572x; 1.1443x over previous
#include <cuda_runtime.h>
#include <cuda_bf16.h>
#include <cstdint>

// Problem constants
#define QN      4
#define KCODES  512
#define DDIM    256
#define HH      1024
#define WW      4
#define BB      16
#define TILE_H  32
#define ROWS    128
#define NROWS   65536
#define NCTA    512
#define NTHR    256
#define CTILE   64        // codes per B tile
#define NTILE   8         // KCODES/CTILE

#define IDX_OFF   (NROWS*DDIM)
#define LOSS_OFF  (IDX_OFF + NROWS*QN)

// smem layout (bytes). A/B row stride = 264 bf16 = 528B = 132 words (132%32==4
// => fragment loads bank = 4*gid + tk, a permutation: conflict-free)
#define ASTRW 132
#define OFF_AHI  0
#define OFF_ALO  67584
#define OFF_BHI  135168
#define OFF_BLO  168960
#define OFF_CN   202752
#define OFF_R2   204800
#define OFF_CAND 205312
#define OFF_DC   206336
#define OFF_SIDX 207360
#define OFF_RSUM 207872
#define OFF_LAST 208384
#define SMEM_BYTES (OFF_LAST + 16)

__device__ float g_norms[QN*KCODES];
__device__ float g_loss_part[NCTA][QN];
__device__ int   g_done = 0;
__device__ float g_resid[(long)NROWS * DDIM];            // 64MB residual scratch
__device__ uint4 g_cbh4[QN*KCODES*DDIM/8];               // bf16 hi codebook (1MB)
__device__ uint4 g_cbl4[QN*KCODES*DDIM/8];               // bf16 lo codebook (1MB)

// m16n8k16 bf16 MMA (sm_80+ baseline instruction, no 'a' target needed)
__device__ __forceinline__ void mma16816(float* d, uint32_t a0, uint32_t a1,
                                         uint32_t a2, uint32_t a3,
                                         uint32_t b0, uint32_t b1) {
    asm volatile(
        "mma.sync.aligned.m16n8k16.row.col.f32.bf16.bf16.f32 "
        "{%0,%1,%2,%3}, {%4,%5,%6,%7}, {%8,%9}, {%0,%1,%2,%3};"
        : "+f"(d[0]), "+f"(d[1]), "+f"(d[2]), "+f"(d[3])
        : "r"(a0), "r"(a1), "r"(a2), "r"(a3), "r"(b0), "r"(b1));
}

__device__ __forceinline__ void upd2(float &b0, int &i0, float &b1, int &i1,
                                     float sc, int gi) {
    if (sc < b0 || (sc == b0 && gi < i0)) { b1 = b0; i1 = i0; b0 = sc; i0 = gi; }
    else if (sc < b1 || (sc == b1 && gi < i1)) { b1 = sc; i1 = gi; }
}

// pack 8 floats -> 8 bf16 (comp 0 = hi, 1 = lo residue)
__device__ __forceinline__ uint4 pack8(const float4 &v0, const float4 &v1, int comp) {
    float f[8] = {v0.x, v0.y, v0.z, v0.w, v1.x, v1.y, v1.z, v1.w};
    unsigned short u[8];
    #pragma unroll
    for (int i = 0; i < 8; ++i) {
        __nv_bfloat16 h = __float2bfloat16(f[i]);
        if (comp) h = __float2bfloat16(f[i] - __bfloat162float(h));
        u[i] = __bfloat16_as_ushort(h);
    }
    uint4 o;
    o.x = (uint32_t)u[0] | ((uint32_t)u[1] << 16);
    o.y = (uint32_t)u[2] | ((uint32_t)u[3] << 16);
    o.z = (uint32_t)u[4] | ((uint32_t)u[5] << 16);
    o.w = (uint32_t)u[6] | ((uint32_t)u[7] << 16);
    return o;
}

// ---------------- code norms: XLA-GPU row-reduce emulation (FROZEN) ----------------
__global__ void rvq_norms_kernel(const float* __restrict__ cb) {
    int warp = (blockIdx.x * blockDim.x + threadIdx.x) >> 5;
    int lane = threadIdx.x & 31;
    if (warp >= QN * KCODES) return;
    const float* row = cb + (long)warp * DDIM;
    float s = 0.f;
    #pragma unroll
    for (int i = 0; i < 8; ++i) {
        float v = __ldg(&row[lane + 32 * i]);
        s = __fadd_rn(s, __fmul_rn(v, v));
    }
    #pragma unroll
    for (int off = 16; off >= 1; off >>= 1)
        s = __fadd_rn(s, __shfl_down_sync(0xffffffffu, s, off));
    if (lane == 0) g_norms[warp] = s;
}

// ---------------- prep: codebook -> bf16 hi/lo (linear [q][code][k]) ----------------
__global__ void rvq_prep_kernel(const float* __restrict__ cb) {
    int cid = blockIdx.x * blockDim.x + threadIdx.x;   // 65536 chunks of 8
    if (cid >= QN * KCODES * DDIM / 8) return;
    const float4* src = reinterpret_cast<const float4*>(cb) + cid * 2;
    float4 v0 = __ldg(&src[0]);
    float4 v1 = __ldg(&src[1]);
    g_cbh4[cid] = pack8(v0, v1, 0);
    g_cbl4[cid] = pack8(v0, v1, 1);
}

// ---------------- main fused RVQ (HMMA scan + FROZEN exact paths) ----------------
__global__ __launch_bounds__(NTHR, 1)
void rvq_main_kernel(const float* __restrict__ x, const float* __restrict__ cb,
                     float* __restrict__ out, int out_size) {
    extern __shared__ char smem[];
    const int tid  = threadIdx.x;
    const int wid  = tid >> 5;
    const int lane = tid & 31;
    const int gid  = lane >> 2;    // 0..7
    const int tk   = lane & 3;     // 0..3
    const int m0   = wid * 16;     // warp's row block
    const int cta  = blockIdx.x;
    const int b    = cta >> 5;
    const int h0   = (cta & 31) * TILE_H;
    const long rb  = (long)cta * ROWS * DDIM;

    float* Scn   = reinterpret_cast<float*>(smem + OFF_CN);
    float* Sr2   = reinterpret_cast<float*>(smem + OFF_R2);
    int*   Scand = reinterpret_cast<int*>(smem + OFF_CAND);   // [2][128]
    float* Sdc   = reinterpret_cast<float*>(smem + OFF_DC);   // [2][128]
    int*   Ssidx = reinterpret_cast<int*>(smem + OFF_SIDX);
    float* Srsum = reinterpret_cast<float*>(smem + OFF_RSUM);
    int*   Slast = reinterpret_cast<int*>(smem + OFF_LAST);

    const uint32_t* SAh = reinterpret_cast<const uint32_t*>(smem + OFF_AHI);
    const uint32_t* SAl = reinterpret_cast<const uint32_t*>(smem + OFF_ALO);
    const uint32_t* SBh = reinterpret_cast<const uint32_t*>(smem + OFF_BHI);
    const uint32_t* SBl = reinterpret_cast<const uint32_t*>(smem + OFF_BLO);

    // ---- init residual = gathered x, staged through smem (A area, 128KB) ----
    {
        float* stage = reinterpret_cast<float*>(smem + OFF_AHI);   // [256][128]
        const float4* x4 = reinterpret_cast<const float4*>(x);
        for (int t = tid; t < DDIM * 32; t += NTHR) {
            int c = t >> 5, f4c = t & 31;
            float4 v = __ldg(&x4[((long)(b * DDIM + c)) * HH + h0 + f4c]);
            float* d = &stage[c * ROWS + f4c * 4];
            d[0] = v.x; d[1] = v.y; d[2] = v.z; d[3] = v.w;
        }
        __syncthreads();
        int lr = tid >> 1, half = tid & 1;
        for (int k0 = half * 128; k0 < half * 128 + 128; k0 += 4) {
            float4 o = make_float4(stage[(k0+0)*ROWS+lr], stage[(k0+1)*ROWS+lr],
                                   stage[(k0+2)*ROWS+lr], stage[(k0+3)*ROWS+lr]);
            *reinterpret_cast<float4*>(&g_resid[rb + (long)lr * DDIM + k0]) = o;
        }
        __syncthreads();
    }

    const bool write_idx = (out_size >= IDX_OFF + NROWS * QN);

    for (int q = 0; q < QN; ++q) {
        // ---- ||r||^2, XLA-GPU order (FROZEN), warp-per-row ----
        #pragma unroll
        for (int pass = 0; pass < 16; ++pass) {
            int row = pass * 8 + wid;
            const float* rr = &g_resid[rb + (long)row * DDIM];
            float s = 0.f;
            #pragma unroll
            for (int i = 0; i < 8; ++i) {
                float v = rr[lane + 32 * i];
                s = __fadd_rn(s, __fmul_rn(v, v));
            }
            #pragma unroll
            for (int off = 16; off >= 1; off >>= 1)
                s = __fadd_rn(s, __shfl_down_sync(0xffffffffu, s, off));
            if (lane == 0) Sr2[row] = s;
        }

        // ---- pack A_hi/A_lo from residual (row stride 528B, 16B-aligned) ----
        {
            int r = tid >> 1, half = tid & 1;
            uint4* dAh = reinterpret_cast<uint4*>(smem + OFF_AHI);
            uint4* dAl = reinterpret_cast<uint4*>(smem + OFF_ALO);
            #pragma unroll
            for (int k0 = half * 128; k0 < half * 128 + 128; k0 += 8) {
                const float4* src = reinterpret_cast<const float4*>(
                    &g_resid[rb + (long)r * DDIM + k0]);
                float4 v0 = src[0], v1 = src[1];
                int di = r * 33 + (k0 >> 3);           // (r*528 + k0*2)/16
                dAh[di] = pack8(v0, v1, 0);
                dAl[di] = pack8(v0, v1, 1);
            }
        }
        for (int i = tid; i < KCODES; i += NTHR) Scn[i] = g_norms[q * KCODES + i];
        __syncthreads();

        // per-thread top-2 for rows rA = m0+gid, rB = rA+8
        float b0A = 3.4e38f, b1A = 3.4e38f, b0B = 3.4e38f, b1B = 3.4e38f;
        int   i0A = 0x7fffffff, i1A = 0x7fffffff, i0B = 0x7fffffff, i1B = 0x7fffffff;

        for (int ct = 0; ct < NTILE; ++ct) {
            // ---- copy B tile (64 codes, hi+lo) into smem ----
            {
                const uint4* srcH = &g_cbh4[(q * KCODES + ct * CTILE) * DDIM / 8];
                const uint4* srcL = &g_cbl4[(q * KCODES + ct * CTILE) * DDIM / 8];
                uint4* dBh = reinterpret_cast<uint4*>(smem + OFF_BHI);
                uint4* dBl = reinterpret_cast<uint4*>(smem + OFF_BLO);
                #pragma unroll
                for (int it = 0; it < 8; ++it) {
                    int i = tid + it * NTHR;           // 2048 chunks
                    int code = i >> 5, kc = i & 31;
                    int di = code * 33 + kc;
                    dBh[di] = __ldg(&srcH[i]);
                    dBl[di] = __ldg(&srcL[i]);
                }
            }
            __syncthreads();

            float acc[8][4];
            #pragma unroll
            for (int j = 0; j < 8; ++j)
                #pragma unroll
                for (int v = 0; v < 4; ++v) acc[j][v] = 0.f;

            #pragma unroll
            for (int pass = 0; pass < 4; ++pass) {
                const uint32_t* Ab = (pass < 2) ? SAh : SAl;
                const uint32_t* Bb = (pass & 1) ? SBl : SBh;
                #pragma unroll 4
                for (int ks = 0; ks < 16; ++ks) {
                    int kw = ks * 8 + tk;
                    int aw = (m0 + gid) * ASTRW + kw;
                    uint32_t a0 = Ab[aw];
                    uint32_t a1 = Ab[aw + 8 * ASTRW];
                    uint32_t a2 = Ab[aw + 4];
                    uint32_t a3 = Ab[aw + 8 * ASTRW + 4];
                    #pragma unroll
                    for (int j = 0; j < 8; ++j) {
                        int bw = (j * 8 + gid) * ASTRW + kw;
                        mma16816(acc[j], a0, a1, a2, a3, Bb[bw], Bb[bw + 4]);
                    }
                }
            }

            // ---- scores + top-2 (selection only; rescore fixes exact values) ----
            #pragma unroll
            for (int j = 0; j < 8; ++j) {
                int c0 = ct * CTILE + j * 8 + tk * 2;
                float n0 = Scn[c0], n1 = Scn[c0 + 1];
                upd2(b0A, i0A, b1A, i1A, fmaf(-2.f, acc[j][0], n0), c0);
                upd2(b0A, i0A, b1A, i1A, fmaf(-2.f, acc[j][1], n1), c0 + 1);
                upd2(b0B, i0B, b1B, i1B, fmaf(-2.f, acc[j][2], n0), c0);
                upd2(b0B, i0B, b1B, i1B, fmaf(-2.f, acc[j][3], n1), c0 + 1);
            }
            __syncthreads();   // B reads done before next tile overwrite
        }

        // merge top-2 across the 4 tk-lanes of each row
        #pragma unroll
        for (int off = 1; off <= 2; off <<= 1) {
            float ob0A = __shfl_xor_sync(0xffffffffu, b0A, off);
            int   oi0A = __shfl_xor_sync(0xffffffffu, i0A, off);
            float ob1A = __shfl_xor_sync(0xffffffffu, b1A, off);
            int   oi1A = __shfl_xor_sync(0xffffffffu, i1A, off);
            float ob0B = __shfl_xor_sync(0xffffffffu, b0B, off);
            int   oi0B = __shfl_xor_sync(0xffffffffu, i0B, off);
            float ob1B = __shfl_xor_sync(0xffffffffu, b1B, off);
            int   oi1B = __shfl_xor_sync(0xffffffffu, i1B, off);
            upd2(b0A, i0A, b1A, i1A, ob0A, oi0A);
            upd2(b0A, i0A, b1A, i1A, ob1A, oi1A);
            upd2(b0B, i0B, b1B, i1B, ob0B, oi0B);
            upd2(b0B, i0B, b1B, i1B, ob1B, oi1B);
        }
        if (tk == 0) {
            int rA = m0 + gid;
            Scand[rA]       = i0A;  Scand[128 + rA]     = i1A;
            Scand[rA + 8]   = i0B;  Scand[128 + rA + 8] = i1B;
        }
        __syncthreads();

        // ---- rescore top-2, cuBLAS-SGEMM arithmetic (FROZEN) ----
        {
            int row = tid >> 1, c = tid & 1;
            int idx = Scand[c * 128 + row];
            const float2* rr = reinterpret_cast<const float2*>(&g_resid[rb + (long)row * DDIM]);
            const float2* crow = reinterpret_cast<const float2*>(
                cb + ((long)(q * KCODES + idx)) * DDIM);
            float acc = 0.f;
            #pragma unroll 8
            for (int kk = 0; kk < 128; ++kk) {
                float2 r = rr[kk];
                float2 cv = __ldg(&crow[kk]);
                acc = fmaf(r.x, cv.x, acc);
                acc = fmaf(r.y, cv.y, acc);
            }
            float tt = __fsub_rn(Sr2[row], __fmul_rn(2.f, acc));
            Sdc[c * 128 + row] = __fadd_rn(tt, g_norms[q * KCODES + idx]);
        }
        __syncthreads();
        if (tid < ROWS) {
            float d0 = Sdc[tid], d1 = Sdc[128 + tid];
            int i0 = Scand[tid], i1 = Scand[128 + tid];
            Ssidx[tid] = (d1 < d0 || (d1 == d0 && i1 < i0)) ? i1 : i0;
        }
        __syncthreads();

        // ---- residual update (exact fp32, FROZEN) ----
        {
            int lr = tid >> 1, half = tid & 1;
            int idx = Ssidx[lr];
            const float4* crow = reinterpret_cast<const float4*>(
                cb + ((long)(q * KCODES + idx)) * DDIM);
            float4* rr = reinterpret_cast<float4*>(&g_resid[rb + (long)lr * DDIM]);
            #pragma unroll
            for (int f4 = half * 32; f4 < half * 32 + 32; ++f4) {
                float4 v = __ldg(&crow[f4]);
                float4 a = rr[f4];
                a.x -= v.x; a.y -= v.y; a.z -= v.z; a.w -= v.w;
                rr[f4] = a;
            }
        }
        if (write_idx && tid < ROWS) {
            int w = tid & 3, hh = tid >> 2;
            long n = ((long)(b * WW + w)) * HH + h0 + hh;
            out[IDX_OFF + n * QN + q] = (float)Ssidx[tid];
        }
        __syncthreads();

        // ---- loss: serial fmaf per row (FROZEN), fixed-order CTA sum ----
        if (tid < ROWS) {
            const float2* rr = reinterpret_cast<const float2*>(&g_resid[rb + (long)tid * DDIM]);
            float s = 0.f;
            #pragma unroll 8
            for (int kk = 0; kk < 128; ++kk) {
                float2 v = rr[kk];
                s = fmaf(v.x, v.x, s);
                s = fmaf(v.y, v.y, s);
            }
            Srsum[tid] = s;
        }
        __syncthreads();
        if (tid == 0) {
            float s = 0.f;
            #pragma unroll
            for (int i = 0; i < ROWS; ++i) s += Srsum[i];
            g_loss_part[cta][q] = s;
        }
        __syncthreads();
    }

    // ---- quantized_out = x - residual_final (exact fp32) ----
    {
        int lr = tid & 127, ks = tid >> 7;
        int w = lr & 3, hh = lr >> 2;
        long n = ((long)(b * WW + w)) * HH + h0 + hh;
        float4* orow = reinterpret_cast<float4*>(out + n * DDIM);
        const float4* rr = reinterpret_cast<const float4*>(&g_resid[rb + (long)lr * DDIM]);
        long cbase = (((long)b * DDIM) * HH + (h0 + hh)) * WW + w;
        #pragma unroll
        for (int f4 = ks * 32; f4 < ks * 32 + 32; ++f4) {
            int c0 = f4 * 4;
            float x0 = __ldg(&x[cbase + (long)(c0 + 0) * (HH * WW)]);
            float x1 = __ldg(&x[cbase + (long)(c0 + 1) * (HH * WW)]);
            float x2 = __ldg(&x[cbase + (long)(c0 + 2) * (HH * WW)]);
            float x3 = __ldg(&x[cbase + (long)(c0 + 3) * (HH * WW)]);
            float4 r = rr[f4];
            orow[f4] = make_float4(x0 - r.x, x1 - r.y, x2 - r.z, x3 - r.w);
        }
    }

    // ---- fused loss finalize: last CTA (fixed-order, FROZEN) ----
    __threadfence();
    __syncthreads();
    if (tid == 0) {
        int old = atomicAdd(&g_done, 1);
        *Slast = (old == (int)gridDim.x - 1) ? 1 : 0;
    }
    __syncthreads();
    if (*Slast) {
        if (out_size >= LOSS_OFF + QN && tid < 128) {
            int q = tid >> 5, ln = tid & 31;
            float s = 0.f;
            for (int i = ln; i < NCTA; i += 32) s += g_loss_part[i][q];
            #pragma unroll
            for (int off = 16; off; off >>= 1)
                s += __shfl_xor_sync(0xffffffffu, s, off);
            if (ln == 0) out[LOSS_OFF + q] = s / (float)(NROWS * DDIM);
        }
        if (tid == 0) g_done = 0;
    }
}

extern "C" void kernel_launch(void* const* d_in, const int* in_sizes, int n_in,
                              void* d_out, int out_size) {
    const float* x  = (const float*)d_in[0];
    const float* cb = (const float*)d_in[1];
    float* out = (float*)d_out;

    cudaFuncSetAttribute(rvq_main_kernel,
                         cudaFuncAttributeMaxDynamicSharedMemorySize, (int)SMEM_BYTES);

    rvq_norms_kernel<<<(QN*KCODES*32 + 255)/256, 256>>>(cb);
    rvq_prep_kernel<<<(QN*KCODES*DDIM/8 + 255)/256, 256>>>(cb);
    rvq_main_kernel<<<NCTA, NTHR, SMEM_BYTES>>>(x, cb, out, out_size);
}

// round 11
// speedup vs baseline: 4.0609x; 1.0528x over previous
#include <cuda_runtime.h>
#include <cuda_bf16.h>
#include <cstdint>

// Problem constants
#define QN      4
#define KCODES  512
#define DDIM    256
#define HH      1024
#define WW      4
#define BB      16
#define TILE_H  32
#define ROWS    128
#define NROWS   65536
#define NCTA    512
#define NTHR    256
#define CTILE   32        // codes per B tile
#define NTILE   16        // KCODES/CTILE

#define IDX_OFF   (NROWS*DDIM)
#define LOSS_OFF  (IDX_OFF + NROWS*QN)

// smem layout (bytes). A/B row stride = 264 bf16 = 528B = 132 words (33 uint4)
#define ASTRW 132
#define BTILE_BYTES 16896              // 32 codes * 528B
#define OFF_AHI  0
#define OFF_ALO  67584
#define OFF_B    135168                // [BHI0][BLO0][BHI1][BLO1]
#define OFF_CN   202752
#define OFF_R2   204800
#define OFF_CAND 205312
#define OFF_DC   206336
#define OFF_SIDX 207360
#define OFF_RSUM 207872
#define OFF_LAST 208384
#define SMEM_BYTES (OFF_LAST + 16)

__device__ float g_norms[QN*KCODES];
__device__ float g_loss_part[NCTA][QN];
__device__ int   g_done = 0;
__device__ float g_resid[(long)NROWS * DDIM];            // 64MB residual scratch
__device__ uint4 g_cbh4[QN*KCODES*DDIM/8];               // bf16 hi codebook (1MB)
__device__ uint4 g_cbl4[QN*KCODES*DDIM/8];               // bf16 lo codebook (1MB)

__device__ __forceinline__ uint32_t smem_to_u32(const void* p) {
    uint32_t a;
    asm("{ .reg .u64 t; cvta.to.shared.u64 t, %1; cvt.u32.u64 %0, t; }" : "=r"(a) : "l"(p));
    return a;
}
#define CP_ASYNC16(dst, src) \
    asm volatile("cp.async.cg.shared.global [%0], [%1], 16;" :: "r"(dst), "l"(src))
#define CP_COMMIT() asm volatile("cp.async.commit_group;" ::: "memory")
#define CP_WAIT0()  asm volatile("cp.async.wait_group 0;" ::: "memory")

// m16n8k16 bf16 MMA (sm_80+ baseline instruction)
__device__ __forceinline__ void mma16816(float* d, uint32_t a0, uint32_t a1,
                                         uint32_t a2, uint32_t a3,
                                         uint32_t b0, uint32_t b1) {
    asm volatile(
        "mma.sync.aligned.m16n8k16.row.col.f32.bf16.bf16.f32 "
        "{%0,%1,%2,%3}, {%4,%5,%6,%7}, {%8,%9}, {%0,%1,%2,%3};"
        : "+f"(d[0]), "+f"(d[1]), "+f"(d[2]), "+f"(d[3])
        : "r"(a0), "r"(a1), "r"(a2), "r"(a3), "r"(b0), "r"(b1));
}

__device__ __forceinline__ void upd2(float &b0, int &i0, float &b1, int &i1,
                                     float sc, int gi) {
    if (sc < b0 || (sc == b0 && gi < i0)) { b1 = b0; i1 = i0; b0 = sc; i0 = gi; }
    else if (sc < b1 || (sc == b1 && gi < i1)) { b1 = sc; i1 = gi; }
}

// pack 8 floats -> 8 bf16 (comp 0 = hi, 1 = lo residue)
__device__ __forceinline__ uint4 pack8(const float4 &v0, const float4 &v1, int comp) {
    float f[8] = {v0.x, v0.y, v0.z, v0.w, v1.x, v1.y, v1.z, v1.w};
    unsigned short u[8];
    #pragma unroll
    for (int i = 0; i < 8; ++i) {
        __nv_bfloat16 h = __float2bfloat16(f[i]);
        if (comp) h = __float2bfloat16(f[i] - __bfloat162float(h));
        u[i] = __bfloat16_as_ushort(h);
    }
    uint4 o;
    o.x = (uint32_t)u[0] | ((uint32_t)u[1] << 16);
    o.y = (uint32_t)u[2] | ((uint32_t)u[3] << 16);
    o.z = (uint32_t)u[4] | ((uint32_t)u[5] << 16);
    o.w = (uint32_t)u[6] | ((uint32_t)u[7] << 16);
    return o;
}

// ---------------- prep: code norms (FROZEN XLA order) + bf16 hi/lo split ----------------
__global__ void rvq_prep_kernel(const float* __restrict__ cb) {
    int gtid = blockIdx.x * blockDim.x + threadIdx.x;
    // part 1: norms, warp per code
    {
        int warp = gtid >> 5;
        int lane = threadIdx.x & 31;
        if (warp < QN * KCODES) {
            const float* row = cb + (long)warp * DDIM;
            float s = 0.f;
            #pragma unroll
            for (int i = 0; i < 8; ++i) {
                float v = __ldg(&row[lane + 32 * i]);
                s = __fadd_rn(s, __fmul_rn(v, v));
            }
            #pragma unroll
            for (int off = 16; off >= 1; off >>= 1)
                s = __fadd_rn(s, __shfl_down_sync(0xffffffffu, s, off));
            if (lane == 0) g_norms[warp] = s;
        }
    }
    // part 2: hi/lo split, chunk of 8 floats per thread
    if (gtid < QN * KCODES * DDIM / 8) {
        const float4* src = reinterpret_cast<const float4*>(cb) + gtid * 2;
        float4 v0 = __ldg(&src[0]);
        float4 v1 = __ldg(&src[1]);
        g_cbh4[gtid] = pack8(v0, v1, 0);
        g_cbl4[gtid] = pack8(v0, v1, 1);
    }
}

// ---------------- main fused RVQ (HMMA 3-pass scan + FROZEN exact paths) ----------------
__global__ __launch_bounds__(NTHR, 1)
void rvq_main_kernel(const float* __restrict__ x, const float* __restrict__ cb,
                     float* __restrict__ out, int out_size) {
    extern __shared__ char smem[];
    const uint32_t smem_base = smem_to_u32(smem);
    const int tid  = threadIdx.x;
    const int wid  = tid >> 5;
    const int lane = tid & 31;
    const int gid  = lane >> 2;    // 0..7
    const int tk   = lane & 3;     // 0..3
    const int m0   = wid * 16;     // warp's row block
    const int cta  = blockIdx.x;
    const int b    = cta >> 5;
    const int h0   = (cta & 31) * TILE_H;
    const long rb  = (long)cta * ROWS * DDIM;

    float* Scn   = reinterpret_cast<float*>(smem + OFF_CN);
    float* Sr2   = reinterpret_cast<float*>(smem + OFF_R2);
    int*   Scand = reinterpret_cast<int*>(smem + OFF_CAND);   // [2][128]
    float* Sdc   = reinterpret_cast<float*>(smem + OFF_DC);   // [2][128]
    int*   Ssidx = reinterpret_cast<int*>(smem + OFF_SIDX);
    float* Srsum = reinterpret_cast<float*>(smem + OFF_RSUM);
    int*   Slast = reinterpret_cast<int*>(smem + OFF_LAST);

    const uint32_t* SAh = reinterpret_cast<const uint32_t*>(smem + OFF_AHI);
    const uint32_t* SAl = reinterpret_cast<const uint32_t*>(smem + OFF_ALO);

    // ---- init residual = gathered x, staged through smem (A area) ----
    {
        float* stage = reinterpret_cast<float*>(smem + OFF_AHI);   // [256][128]
        const float4* x4 = reinterpret_cast<const float4*>(x);
        for (int t = tid; t < DDIM * 32; t += NTHR) {
            int c = t >> 5, f4c = t & 31;
            float4 v = __ldg(&x4[((long)(b * DDIM + c)) * HH + h0 + f4c]);
            float* d = &stage[c * ROWS + f4c * 4];
            d[0] = v.x; d[1] = v.y; d[2] = v.z; d[3] = v.w;
        }
        __syncthreads();
        int lr = tid >> 1, half = tid & 1;
        for (int k0 = half * 128; k0 < half * 128 + 128; k0 += 4) {
            float4 o = make_float4(stage[(k0+0)*ROWS+lr], stage[(k0+1)*ROWS+lr],
                                   stage[(k0+2)*ROWS+lr], stage[(k0+3)*ROWS+lr]);
            *reinterpret_cast<float4*>(&g_resid[rb + (long)lr * DDIM + k0]) = o;
        }
        __syncthreads();
    }

    const bool write_idx = (out_size >= IDX_OFF + NROWS * QN);

    for (int q = 0; q < QN; ++q) {
        // ---- ||r||^2, XLA-GPU order (FROZEN), warp-per-row ----
        #pragma unroll
        for (int pass = 0; pass < 16; ++pass) {
            int row = pass * 8 + wid;
            const float* rr = &g_resid[rb + (long)row * DDIM];
            float s = 0.f;
            #pragma unroll
            for (int i = 0; i < 8; ++i) {
                float v = rr[lane + 32 * i];
                s = __fadd_rn(s, __fmul_rn(v, v));
            }
            #pragma unroll
            for (int off = 16; off >= 1; off >>= 1)
                s = __fadd_rn(s, __shfl_down_sync(0xffffffffu, s, off));
            if (lane == 0) Sr2[row] = s;
        }

        // ---- pack A_hi/A_lo from residual (row stride 528B) ----
        {
            int r = tid >> 1, half = tid & 1;
            uint4* dAh = reinterpret_cast<uint4*>(smem + OFF_AHI);
            uint4* dAl = reinterpret_cast<uint4*>(smem + OFF_ALO);
            #pragma unroll
            for (int k0 = half * 128; k0 < half * 128 + 128; k0 += 8) {
                const float4* src = reinterpret_cast<const float4*>(
                    &g_resid[rb + (long)r * DDIM + k0]);
                float4 v0 = src[0], v1 = src[1];
                int di = r * 33 + (k0 >> 3);
                dAh[di] = pack8(v0, v1, 0);
                dAl[di] = pack8(v0, v1, 1);
            }
        }
        for (int i = tid; i < KCODES; i += NTHR) Scn[i] = g_norms[q * KCODES + i];

        // prefetch B tile 0 into buffer 0
        {
            const uint4* srcH = &g_cbh4[(long)(q * KCODES) * 32];
            const uint4* srcL = &g_cbl4[(long)(q * KCODES) * 32];
            uint32_t dH = smem_base + OFF_B;
            uint32_t dL = dH + BTILE_BYTES;
            #pragma unroll
            for (int it = 0; it < 5; ++it) {
                int i = tid + it * NTHR;
                if (i < 1056) {
                    int code = i / 33, kc = i - code * 33;
                    if (kc < 32) {
                        CP_ASYNC16(dH + (code * 33 + kc) * 16, &srcH[code * 32 + kc]);
                        CP_ASYNC16(dL + (code * 33 + kc) * 16, &srcL[code * 32 + kc]);
                    }
                }
            }
            CP_COMMIT();
        }
        __syncthreads();   // A tiles + Scn ready

        // per-thread top-2 for rows rA = m0+gid, rB = rA+8
        float b0A = 3.4e38f, b1A = 3.4e38f, b0B = 3.4e38f, b1B = 3.4e38f;
        int   i0A = 0x7fffffff, i1A = 0x7fffffff, i0B = 0x7fffffff, i1B = 0x7fffffff;

        for (int ct = 0; ct < NTILE; ++ct) {
            CP_WAIT0();
            __syncthreads();   // tile ct arrived; previous compute done everywhere

            if (ct + 1 < NTILE) {
                const uint4* srcH = &g_cbh4[(long)(q * KCODES + (ct + 1) * CTILE) * 32];
                const uint4* srcL = &g_cbl4[(long)(q * KCODES + (ct + 1) * CTILE) * 32];
                uint32_t dH = smem_base + OFF_B + ((ct + 1) & 1) * 2 * BTILE_BYTES;
                uint32_t dL = dH + BTILE_BYTES;
                #pragma unroll
                for (int it = 0; it < 5; ++it) {
                    int i = tid + it * NTHR;
                    if (i < 1056) {
                        int code = i / 33, kc = i - code * 33;
                        if (kc < 32) {
                            CP_ASYNC16(dH + (code * 33 + kc) * 16, &srcH[code * 32 + kc]);
                            CP_ASYNC16(dL + (code * 33 + kc) * 16, &srcL[code * 32 + kc]);
                        }
                    }
                }
                CP_COMMIT();
            }

            const uint32_t* SBh = reinterpret_cast<const uint32_t*>(
                smem + OFF_B + (ct & 1) * 2 * BTILE_BYTES);
            const uint32_t* SBl = SBh + BTILE_BYTES / 4;

            float acc[4][4];
            #pragma unroll
            for (int j = 0; j < 4; ++j)
                #pragma unroll
                for (int v = 0; v < 4; ++v) acc[j][v] = 0.f;

            // 3 passes: hh, h*lo(B), lo(A)*h  (ll dropped: ~6e-5 score noise)
            #pragma unroll
            for (int pass = 0; pass < 3; ++pass) {
                const uint32_t* Ab = (pass == 2) ? SAl : SAh;
                const uint32_t* Bb = (pass == 1) ? SBl : SBh;
                #pragma unroll 4
                for (int ks = 0; ks < 16; ++ks) {
                    int kw = ks * 8 + tk;
                    int aw = (m0 + gid) * ASTRW + kw;
                    uint32_t a0 = Ab[aw];
                    uint32_t a1 = Ab[aw + 8 * ASTRW];
                    uint32_t a2 = Ab[aw + 4];
                    uint32_t a3 = Ab[aw + 8 * ASTRW + 4];
                    #pragma unroll
                    for (int j = 0; j < 4; ++j) {
                        int bw = (j * 8 + gid) * ASTRW + kw;
                        mma16816(acc[j], a0, a1, a2, a3, Bb[bw], Bb[bw + 4]);
                    }
                }
            }

            // scores + top-2 (selection only; frozen rescore fixes exact values)
            #pragma unroll
            for (int j = 0; j < 4; ++j) {
                int c0 = ct * CTILE + j * 8 + tk * 2;
                float n0 = Scn[c0], n1 = Scn[c0 + 1];
                upd2(b0A, i0A, b1A, i1A, fmaf(-2.f, acc[j][0], n0), c0);
                upd2(b0A, i0A, b1A, i1A, fmaf(-2.f, acc[j][1], n1), c0 + 1);
                upd2(b0B, i0B, b1B, i1B, fmaf(-2.f, acc[j][2], n0), c0);
                upd2(b0B, i0B, b1B, i1B, fmaf(-2.f, acc[j][3], n1), c0 + 1);
            }
        }

        // merge top-2 across the 4 tk-lanes of each row
        #pragma unroll
        for (int off = 1; off <= 2; off <<= 1) {
            float ob0A = __shfl_xor_sync(0xffffffffu, b0A, off);
            int   oi0A = __shfl_xor_sync(0xffffffffu, i0A, off);
            float ob1A = __shfl_xor_sync(0xffffffffu, b1A, off);
            int   oi1A = __shfl_xor_sync(0xffffffffu, i1A, off);
            float ob0B = __shfl_xor_sync(0xffffffffu, b0B, off);
            int   oi0B = __shfl_xor_sync(0xffffffffu, i0B, off);
            float ob1B = __shfl_xor_sync(0xffffffffu, b1B, off);
            int   oi1B = __shfl_xor_sync(0xffffffffu, i1B, off);
            upd2(b0A, i0A, b1A, i1A, ob0A, oi0A);
            upd2(b0A, i0A, b1A, i1A, ob1A, oi1A);
            upd2(b0B, i0B, b1B, i1B, ob0B, oi0B);
            upd2(b0B, i0B, b1B, i1B, ob1B, oi1B);
        }
        if (tk == 0) {
            int rA = m0 + gid;
            Scand[rA]       = i0A;  Scand[128 + rA]     = i1A;
            Scand[rA + 8]   = i0B;  Scand[128 + rA + 8] = i1B;
        }
        __syncthreads();

        // ---- rescore top-2, cuBLAS-SGEMM arithmetic (FROZEN) ----
        {
            int row = tid >> 1, c = tid & 1;
            int idx = Scand[c * 128 + row];
            const float2* rr = reinterpret_cast<const float2*>(&g_resid[rb + (long)row * DDIM]);
            const float2* crow = reinterpret_cast<const float2*>(
                cb + ((long)(q * KCODES + idx)) * DDIM);
            float acc = 0.f;
            #pragma unroll 8
            for (int kk = 0; kk < 128; ++kk) {
                float2 r = rr[kk];
                float2 cv = __ldg(&crow[kk]);
                acc = fmaf(r.x, cv.x, acc);
                acc = fmaf(r.y, cv.y, acc);
            }
            float tt = __fsub_rn(Sr2[row], __fmul_rn(2.f, acc));
            Sdc[c * 128 + row] = __fadd_rn(tt, g_norms[q * KCODES + idx]);
        }
        __syncthreads();
        if (tid < ROWS) {
            float d0 = Sdc[tid], d1 = Sdc[128 + tid];
            int i0 = Scand[tid], i1 = Scand[128 + tid];
            Ssidx[tid] = (d1 < d0 || (d1 == d0 && i1 < i0)) ? i1 : i0;
        }
        __syncthreads();

        // ---- residual update (exact fp32, FROZEN) ----
        {
            int lr = tid >> 1, half = tid & 1;
            int idx = Ssidx[lr];
            const float4* crow = reinterpret_cast<const float4*>(
                cb + ((long)(q * KCODES + idx)) * DDIM);
            float4* rr = reinterpret_cast<float4*>(&g_resid[rb + (long)lr * DDIM]);
            #pragma unroll
            for (int f4 = half * 32; f4 < half * 32 + 32; ++f4) {
                float4 v = __ldg(&crow[f4]);
                float4 a = rr[f4];
                a.x -= v.x; a.y -= v.y; a.z -= v.z; a.w -= v.w;
                rr[f4] = a;
            }
        }
        if (write_idx && tid < ROWS) {
            int w = tid & 3, hh = tid >> 2;
            long n = ((long)(b * WW + w)) * HH + h0 + hh;
            out[IDX_OFF + n * QN + q] = (float)Ssidx[tid];
        }
        __syncthreads();

        // ---- loss: serial fmaf per row (FROZEN), fixed-order CTA sum ----
        if (tid < ROWS) {
            const float2* rr = reinterpret_cast<const float2*>(&g_resid[rb + (long)tid * DDIM]);
            float s = 0.f;
            #pragma unroll 8
            for (int kk = 0; kk < 128; ++kk) {
                float2 v = rr[kk];
                s = fmaf(v.x, v.x, s);
                s = fmaf(v.y, v.y, s);
            }
            Srsum[tid] = s;
        }
        __syncthreads();
        if (tid == 0) {
            float s = 0.f;
            #pragma unroll
            for (int i = 0; i < ROWS; ++i) s += Srsum[i];
            g_loss_part[cta][q] = s;
        }
        __syncthreads();
    }

    // ---- quantized_out = x - residual_final (exact fp32) ----
    {
        int lr = tid & 127, ks = tid >> 7;
        int w = lr & 3, hh = lr >> 2;
        long n = ((long)(b * WW + w)) * HH + h0 + hh;
        float4* orow = reinterpret_cast<float4*>(out + n * DDIM);
        const float4* rr = reinterpret_cast<const float4*>(&g_resid[rb + (long)lr * DDIM]);
        long cbase = (((long)b * DDIM) * HH + (h0 + hh)) * WW + w;
        #pragma unroll
        for (int f4 = ks * 32; f4 < ks * 32 + 32; ++f4) {
            int c0 = f4 * 4;
            float x0 = __ldg(&x[cbase + (long)(c0 + 0) * (HH * WW)]);
            float x1 = __ldg(&x[cbase + (long)(c0 + 1) * (HH * WW)]);
            float x2 = __ldg(&x[cbase + (long)(c0 + 2) * (HH * WW)]);
            float x3 = __ldg(&x[cbase + (long)(c0 + 3) * (HH * WW)]);
            float4 r = rr[f4];
            orow[f4] = make_float4(x0 - r.x, x1 - r.y, x2 - r.z, x3 - r.w);
        }
    }

    // ---- fused loss finalize: last CTA (fixed-order, FROZEN) ----
    __threadfence();
    __syncthreads();
    if (tid == 0) {
        int old = atomicAdd(&g_done, 1);
        *Slast = (old == (int)gridDim.x - 1) ? 1 : 0;
    }
    __syncthreads();
    if (*Slast) {
        if (out_size >= LOSS_OFF + QN && tid < 128) {
            int q = tid >> 5, ln = tid & 31;
            float s = 0.f;
            for (int i = ln; i < NCTA; i += 32) s += g_loss_part[i][q];
            #pragma unroll
            for (int off = 16; off; off >>= 1)
                s += __shfl_xor_sync(0xffffffffu, s, off);
            if (ln == 0) out[LOSS_OFF + q] = s / (float)(NROWS * DDIM);
        }
        if (tid == 0) g_done = 0;
    }
}

extern "C" void kernel_launch(void* const* d_in, const int* in_sizes, int n_in,
                              void* d_out, int out_size) {
    const float* x  = (const float*)d_in[0];
    const float* cb = (const float*)d_in[1];
    float* out = (float*)d_out;

    cudaFuncSetAttribute(rvq_main_kernel,
                         cudaFuncAttributeMaxDynamicSharedMemorySize, (int)SMEM_BYTES);

    rvq_prep_kernel<<<(QN*KCODES*32 + 255)/256, 256>>>(cb);
    rvq_main_kernel<<<NCTA, NTHR, SMEM_BYTES>>>(x, cb, out, out_size);
}

// round 12
// speedup vs baseline: 4.6955x; 1.1563x over previous
#include <cuda_runtime.h>
#include <cuda_bf16.h>
#include <cstdint>

// Problem constants
#define QN      4
#define KCODES  512
#define DDIM    256
#define HH      1024
#define WW      4
#define BB      16
#define TILE_H  32
#define ROWS    128
#define NROWS   65536
#define NCTA    512
#define NTHR    256
#define CTILE   64        // codes per B tile
#define NTILE   8         // KCODES/CTILE

#define IDX_OFF   (NROWS*DDIM)
#define LOSS_OFF  (IDX_OFF + NROWS*QN)

// smem layout (bytes). Row stride 528B = 132 words (33 uint4): ldmatrix phases
// read 8 rows starting at banks {4r mod 32} -> conflict-free.
#define RSTR  528
#define BHALF 33792                    // 64 codes * 528
#define BBUF  67584                    // hi + lo
#define OFF_ALO  0
#define OFF_B    67584                 // two buffers of BBUF (also A_hi temp / x stage)
#define OFF_CN   202752
#define OFF_R2   204800
#define OFF_CAND 205312
#define OFF_DC   206336
#define OFF_SIDX 207360
#define OFF_RSUM 207872
#define OFF_LAST 208384
#define SMEM_BYTES (OFF_LAST + 16)

__device__ float g_norms[QN*KCODES];
__device__ float g_loss_part[NCTA][QN];
__device__ int   g_done = 0;
__device__ float g_resid[(long)NROWS * DDIM];            // 64MB residual scratch
__device__ uint4 g_cbh4[QN*KCODES*DDIM/8];               // bf16 hi codebook (1MB)
__device__ uint4 g_cbl4[QN*KCODES*DDIM/8];               // bf16 lo codebook (1MB)

__device__ __forceinline__ uint32_t smem_to_u32(const void* p) {
    uint32_t a;
    asm("{ .reg .u64 t; cvta.to.shared.u64 t, %1; cvt.u32.u64 %0, t; }" : "=r"(a) : "l"(p));
    return a;
}
#define CP_ASYNC16(dst, src) \
    asm volatile("cp.async.cg.shared.global [%0], [%1], 16;" :: "r"(dst), "l"(src))
#define CP_COMMIT() asm volatile("cp.async.commit_group;" ::: "memory")
#define CP_WAIT0()  asm volatile("cp.async.wait_group 0;" ::: "memory")

#define LDSM_X4(r0, r1, r2, r3, addr) \
    asm volatile("ldmatrix.sync.aligned.m8n8.x4.shared.b16 {%0,%1,%2,%3}, [%4];" \
        : "=r"(r0), "=r"(r1), "=r"(r2), "=r"(r3) : "r"(addr))

// m16n8k16 bf16 MMA (sm_80+ baseline instruction)
__device__ __forceinline__ void mma16816(float* d, uint32_t a0, uint32_t a1,
                                         uint32_t a2, uint32_t a3,
                                         uint32_t b0, uint32_t b1) {
    asm volatile(
        "mma.sync.aligned.m16n8k16.row.col.f32.bf16.bf16.f32 "
        "{%0,%1,%2,%3}, {%4,%5,%6,%7}, {%8,%9}, {%0,%1,%2,%3};"
        : "+f"(d[0]), "+f"(d[1]), "+f"(d[2]), "+f"(d[3])
        : "r"(a0), "r"(a1), "r"(a2), "r"(a3), "r"(b0), "r"(b1));
}

__device__ __forceinline__ void upd2(float &b0, int &i0, float &b1, int &i1,
                                     float sc, int gi) {
    if (sc < b0 || (sc == b0 && gi < i0)) { b1 = b0; i1 = i0; b0 = sc; i0 = gi; }
    else if (sc < b1 || (sc == b1 && gi < i1)) { b1 = sc; i1 = gi; }
}

// pack 8 floats -> 8 bf16 (comp 0 = hi, 1 = lo residue)
__device__ __forceinline__ uint4 pack8(const float4 &v0, const float4 &v1, int comp) {
    float f[8] = {v0.x, v0.y, v0.z, v0.w, v1.x, v1.y, v1.z, v1.w};
    unsigned short u[8];
    #pragma unroll
    for (int i = 0; i < 8; ++i) {
        __nv_bfloat16 h = __float2bfloat16(f[i]);
        if (comp) h = __float2bfloat16(f[i] - __bfloat162float(h));
        u[i] = __bfloat16_as_ushort(h);
    }
    uint4 o;
    o.x = (uint32_t)u[0] | ((uint32_t)u[1] << 16);
    o.y = (uint32_t)u[2] | ((uint32_t)u[3] << 16);
    o.z = (uint32_t)u[4] | ((uint32_t)u[5] << 16);
    o.w = (uint32_t)u[6] | ((uint32_t)u[7] << 16);
    return o;
}

// ---------------- prep: code norms (FROZEN XLA order) + bf16 hi/lo split ----------------
__global__ void rvq_prep_kernel(const float* __restrict__ cb) {
    int gtid = blockIdx.x * blockDim.x + threadIdx.x;
    {
        int warp = gtid >> 5;
        int lane = threadIdx.x & 31;
        if (warp < QN * KCODES) {
            const float* row = cb + (long)warp * DDIM;
            float s = 0.f;
            #pragma unroll
            for (int i = 0; i < 8; ++i) {
                float v = __ldg(&row[lane + 32 * i]);
                s = __fadd_rn(s, __fmul_rn(v, v));
            }
            #pragma unroll
            for (int off = 16; off >= 1; off >>= 1)
                s = __fadd_rn(s, __shfl_down_sync(0xffffffffu, s, off));
            if (lane == 0) g_norms[warp] = s;
        }
    }
    if (gtid < QN * KCODES * DDIM / 8) {
        const float4* src = reinterpret_cast<const float4*>(cb) + gtid * 2;
        float4 v0 = __ldg(&src[0]);
        float4 v1 = __ldg(&src[1]);
        g_cbh4[gtid] = pack8(v0, v1, 0);
        g_cbl4[gtid] = pack8(v0, v1, 1);
    }
}

// ---------------- main fused RVQ (ldmatrix/HMMA scan + FROZEN exact paths) ----------------
__global__ __launch_bounds__(NTHR, 1)
void rvq_main_kernel(const float* __restrict__ x, const float* __restrict__ cb,
                     float* __restrict__ out, int out_size) {
    extern __shared__ char smem[];
    const uint32_t smem_base = smem_to_u32(smem);
    const int tid  = threadIdx.x;
    const int wid  = tid >> 5;
    const int lane = tid & 31;
    const int gid  = lane >> 2;    // 0..7
    const int tk   = lane & 3;     // 0..3
    const int m0   = wid * 16;     // warp's row block
    const int cta  = blockIdx.x;
    const int b    = cta >> 5;
    const int h0   = (cta & 31) * TILE_H;
    const long rb  = (long)cta * ROWS * DDIM;

    float* Scn   = reinterpret_cast<float*>(smem + OFF_CN);
    float* Sr2   = reinterpret_cast<float*>(smem + OFF_R2);
    int*   Scand = reinterpret_cast<int*>(smem + OFF_CAND);   // [2][128]
    float* Sdc   = reinterpret_cast<float*>(smem + OFF_DC);   // [2][128]
    int*   Ssidx = reinterpret_cast<int*>(smem + OFF_SIDX);
    float* Srsum = reinterpret_cast<float*>(smem + OFF_RSUM);
    int*   Slast = reinterpret_cast<int*>(smem + OFF_LAST);

    // ldmatrix source addresses (per-thread constants)
    const uint32_t frag_row  = (lane & 15);
    const uint32_t frag_koff = ((lane >> 4) & 1) * 16;
    const uint32_t brow      = ((lane >> 4) & 1) * 8 + (lane & 7);
    const uint32_t bkoff     = ((lane >> 3) & 1) * 16;

    // ---- init residual = gathered x, staged through smem ----
    {
        float* stage = reinterpret_cast<float*>(smem);   // [256][128] at offset 0
        const float4* x4 = reinterpret_cast<const float4*>(x);
        for (int t = tid; t < DDIM * 32; t += NTHR) {
            int c = t >> 5, f4c = t & 31;
            float4 v = __ldg(&x4[((long)(b * DDIM + c)) * HH + h0 + f4c]);
            float* d = &stage[c * ROWS + f4c * 4];
            d[0] = v.x; d[1] = v.y; d[2] = v.z; d[3] = v.w;
        }
        __syncthreads();
        int lr = tid >> 1, half = tid & 1;
        for (int k0 = half * 128; k0 < half * 128 + 128; k0 += 4) {
            float4 o = make_float4(stage[(k0+0)*ROWS+lr], stage[(k0+1)*ROWS+lr],
                                   stage[(k0+2)*ROWS+lr], stage[(k0+3)*ROWS+lr]);
            *reinterpret_cast<float4*>(&g_resid[rb + (long)lr * DDIM + k0]) = o;
        }
        __syncthreads();
    }

    const bool write_idx = (out_size >= IDX_OFF + NROWS * QN);

    for (int q = 0; q < QN; ++q) {
        // ---- ||r||^2, XLA-GPU order (FROZEN), warp-per-row ----
        #pragma unroll
        for (int pass = 0; pass < 16; ++pass) {
            int row = pass * 8 + wid;
            const float* rr = &g_resid[rb + (long)row * DDIM];
            float s = 0.f;
            #pragma unroll
            for (int i = 0; i < 8; ++i) {
                float v = rr[lane + 32 * i];
                s = __fadd_rn(s, __fmul_rn(v, v));
            }
            #pragma unroll
            for (int off = 16; off >= 1; off >>= 1)
                s = __fadd_rn(s, __shfl_down_sync(0xffffffffu, s, off));
            if (lane == 0) Sr2[row] = s;
        }

        // ---- pack A_lo -> OFF_ALO; A_hi -> OFF_B (temp) ----
        {
            int r = tid >> 1, half = tid & 1;
            uint4* dAl = reinterpret_cast<uint4*>(smem + OFF_ALO);
            uint4* dAh = reinterpret_cast<uint4*>(smem + OFF_B);
            #pragma unroll
            for (int k0 = half * 128; k0 < half * 128 + 128; k0 += 8) {
                const float4* src = reinterpret_cast<const float4*>(
                    &g_resid[rb + (long)r * DDIM + k0]);
                float4 v0 = src[0], v1 = src[1];
                int di = r * 33 + (k0 >> 3);
                dAh[di] = pack8(v0, v1, 0);
                dAl[di] = pack8(v0, v1, 1);
            }
        }
        for (int i = tid; i < KCODES; i += NTHR) Scn[i] = g_norms[q * KCODES + i];
        __syncthreads();

        // ---- load persistent A_hi fragments from temp (64 regs) ----
        uint32_t ahi[16][4];
        {
            uint32_t abase = smem_base + OFF_B + frag_row * RSTR + frag_koff;
            #pragma unroll
            for (int ks = 0; ks < 16; ++ks)
                LDSM_X4(ahi[ks][0], ahi[ks][1], ahi[ks][2], ahi[ks][3],
                        abase + m0 * RSTR + ks * 32);
        }
        __syncthreads();   // temp free; B buffers may now be written

        // prefetch B tile 0 into buffer 0
        {
            const uint4* srcH = &g_cbh4[(long)(q * KCODES) * 32];
            const uint4* srcL = &g_cbl4[(long)(q * KCODES) * 32];
            uint32_t d0 = smem_base + OFF_B;
            #pragma unroll
            for (int it = 0; it < 16; ++it) {
                int i = tid + it * NTHR;        // 4096 chunks: [comp][code][kc]
                int comp = i >> 11, r = (i >> 5) & 63, kc = i & 31;
                const uint4* s = comp ? &srcL[r * 32 + kc] : &srcH[r * 32 + kc];
                CP_ASYNC16(d0 + comp * BHALF + (r * 33 + kc) * 16, s);
            }
            CP_COMMIT();
        }

        // per-thread top-2 for rows rA = m0+gid, rB = rA+8
        float b0A = 3.4e38f, b1A = 3.4e38f, b0B = 3.4e38f, b1B = 3.4e38f;
        int   i0A = 0x7fffffff, i1A = 0x7fffffff, i0B = 0x7fffffff, i1B = 0x7fffffff;

        for (int ct = 0; ct < NTILE; ++ct) {
            CP_WAIT0();
            __syncthreads();   // tile ct arrived everywhere; prev compute done

            if (ct + 1 < NTILE) {
                const uint4* srcH = &g_cbh4[(long)(q * KCODES + (ct + 1) * CTILE) * 32];
                const uint4* srcL = &g_cbl4[(long)(q * KCODES + (ct + 1) * CTILE) * 32];
                uint32_t d0 = smem_base + OFF_B + ((ct + 1) & 1) * BBUF;
                #pragma unroll
                for (int it = 0; it < 16; ++it) {
                    int i = tid + it * NTHR;
                    int comp = i >> 11, r = (i >> 5) & 63, kc = i & 31;
                    const uint4* s = comp ? &srcL[r * 32 + kc] : &srcH[r * 32 + kc];
                    CP_ASYNC16(d0 + comp * BHALF + (r * 33 + kc) * 16, s);
                }
                CP_COMMIT();
            }

            const uint32_t bh_base = smem_base + OFF_B + (ct & 1) * BBUF
                                     + brow * RSTR + bkoff;
            const uint32_t al_base = smem_base + OFF_ALO + (m0 + frag_row) * RSTR
                                     + frag_koff;

            float acc[8][4];
            #pragma unroll
            for (int j = 0; j < 8; ++j)
                #pragma unroll
                for (int v = 0; v < 4; ++v) acc[j][v] = 0.f;

            #pragma unroll
            for (int ks = 0; ks < 16; ++ks) {
                uint32_t al[4];
                LDSM_X4(al[0], al[1], al[2], al[3], al_base + ks * 32);
                #pragma unroll
                for (int p = 0; p < 4; ++p) {     // j-pairs (2p, 2p+1)
                    uint32_t bh[4], bl[4];
                    uint32_t ba = bh_base + p * 16 * RSTR + ks * 32;
                    LDSM_X4(bh[0], bh[1], bh[2], bh[3], ba);
                    LDSM_X4(bl[0], bl[1], bl[2], bl[3], ba + BHALF);
                    // hh, h*loB, loA*h  (ll dropped: ~6e-5 score noise)
                    mma16816(acc[2*p],   ahi[ks][0], ahi[ks][1], ahi[ks][2], ahi[ks][3], bh[0], bh[1]);
                    mma16816(acc[2*p],   ahi[ks][0], ahi[ks][1], ahi[ks][2], ahi[ks][3], bl[0], bl[1]);
                    mma16816(acc[2*p],   al[0], al[1], al[2], al[3], bh[0], bh[1]);
                    mma16816(acc[2*p+1], ahi[ks][0], ahi[ks][1], ahi[ks][2], ahi[ks][3], bh[2], bh[3]);
                    mma16816(acc[2*p+1], ahi[ks][0], ahi[ks][1], ahi[ks][2], ahi[ks][3], bl[2], bl[3]);
                    mma16816(acc[2*p+1], al[0], al[1], al[2], al[3], bh[2], bh[3]);
                }
            }

            // scores + top-2 (selection only; frozen rescore fixes exact values)
            #pragma unroll
            for (int j = 0; j < 8; ++j) {
                int c0 = ct * CTILE + j * 8 + tk * 2;
                float n0 = Scn[c0], n1 = Scn[c0 + 1];
                upd2(b0A, i0A, b1A, i1A, fmaf(-2.f, acc[j][0], n0), c0);
                upd2(b0A, i0A, b1A, i1A, fmaf(-2.f, acc[j][1], n1), c0 + 1);
                upd2(b0B, i0B, b1B, i1B, fmaf(-2.f, acc[j][2], n0), c0);
                upd2(b0B, i0B, b1B, i1B, fmaf(-2.f, acc[j][3], n1), c0 + 1);
            }
        }

        // merge top-2 across the 4 tk-lanes of each row
        #pragma unroll
        for (int off = 1; off <= 2; off <<= 1) {
            float ob0A = __shfl_xor_sync(0xffffffffu, b0A, off);
            int   oi0A = __shfl_xor_sync(0xffffffffu, i0A, off);
            float ob1A = __shfl_xor_sync(0xffffffffu, b1A, off);
            int   oi1A = __shfl_xor_sync(0xffffffffu, i1A, off);
            float ob0B = __shfl_xor_sync(0xffffffffu, b0B, off);
            int   oi0B = __shfl_xor_sync(0xffffffffu, i0B, off);
            float ob1B = __shfl_xor_sync(0xffffffffu, b1B, off);
            int   oi1B = __shfl_xor_sync(0xffffffffu, i1B, off);
            upd2(b0A, i0A, b1A, i1A, ob0A, oi0A);
            upd2(b0A, i0A, b1A, i1A, ob1A, oi1A);
            upd2(b0B, i0B, b1B, i1B, ob0B, oi0B);
            upd2(b0B, i0B, b1B, i1B, ob1B, oi1B);
        }
        if (tk == 0) {
            int rA = m0 + gid;
            Scand[rA]       = i0A;  Scand[128 + rA]     = i1A;
            Scand[rA + 8]   = i0B;  Scand[128 + rA + 8] = i1B;
        }
        __syncthreads();

        // ---- rescore top-2, cuBLAS-SGEMM arithmetic (FROZEN) ----
        {
            int row = tid >> 1, c = tid & 1;
            int idx = Scand[c * 128 + row];
            const float2* rr = reinterpret_cast<const float2*>(&g_resid[rb + (long)row * DDIM]);
            const float2* crow = reinterpret_cast<const float2*>(
                cb + ((long)(q * KCODES + idx)) * DDIM);
            float acc = 0.f;
            #pragma unroll 8
            for (int kk = 0; kk < 128; ++kk) {
                float2 r = rr[kk];
                float2 cv = __ldg(&crow[kk]);
                acc = fmaf(r.x, cv.x, acc);
                acc = fmaf(r.y, cv.y, acc);
            }
            float tt = __fsub_rn(Sr2[row], __fmul_rn(2.f, acc));
            Sdc[c * 128 + row] = __fadd_rn(tt, g_norms[q * KCODES + idx]);
        }
        __syncthreads();
        if (tid < ROWS) {
            float d0 = Sdc[tid], d1 = Sdc[128 + tid];
            int i0 = Scand[tid], i1 = Scand[128 + tid];
            Ssidx[tid] = (d1 < d0 || (d1 == d0 && i1 < i0)) ? i1 : i0;
        }
        __syncthreads();

        // ---- residual update (exact fp32, FROZEN) ----
        {
            int lr = tid >> 1, half = tid & 1;
            int idx = Ssidx[lr];
            const float4* crow = reinterpret_cast<const float4*>(
                cb + ((long)(q * KCODES + idx)) * DDIM);
            float4* rr = reinterpret_cast<float4*>(&g_resid[rb + (long)lr * DDIM]);
            #pragma unroll
            for (int f4 = half * 32; f4 < half * 32 + 32; ++f4) {
                float4 v = __ldg(&crow[f4]);
                float4 a = rr[f4];
                a.x -= v.x; a.y -= v.y; a.z -= v.z; a.w -= v.w;
                rr[f4] = a;
            }
        }
        if (write_idx && tid < ROWS) {
            int w = tid & 3, hh = tid >> 2;
            long n = ((long)(b * WW + w)) * HH + h0 + hh;
            out[IDX_OFF + n * QN + q] = (float)Ssidx[tid];
        }
        __syncthreads();

        // ---- loss: serial fmaf per row (FROZEN), fixed-order CTA sum ----
        if (tid < ROWS) {
            const float2* rr = reinterpret_cast<const float2*>(&g_resid[rb + (long)tid * DDIM]);
            float s = 0.f;
            #pragma unroll 8
            for (int kk = 0; kk < 128; ++kk) {
                float2 v = rr[kk];
                s = fmaf(v.x, v.x, s);
                s = fmaf(v.y, v.y, s);
            }
            Srsum[tid] = s;
        }
        __syncthreads();
        if (tid == 0) {
            float s = 0.f;
            #pragma unroll
            for (int i = 0; i < ROWS; ++i) s += Srsum[i];
            g_loss_part[cta][q] = s;
        }
        __syncthreads();
    }

    // ---- quantized_out = x - residual_final (exact fp32) ----
    {
        int lr = tid & 127, ks = tid >> 7;
        int w = lr & 3, hh = lr >> 2;
        long n = ((long)(b * WW + w)) * HH + h0 + hh;
        float4* orow = reinterpret_cast<float4*>(out + n * DDIM);
        const float4* rr = reinterpret_cast<const float4*>(&g_resid[rb + (long)lr * DDIM]);
        long cbase = (((long)b * DDIM) * HH + (h0 + hh)) * WW + w;
        #pragma unroll
        for (int f4 = ks * 32; f4 < ks * 32 + 32; ++f4) {
            int c0 = f4 * 4;
            float x0 = __ldg(&x[cbase + (long)(c0 + 0) * (HH * WW)]);
            float x1 = __ldg(&x[cbase + (long)(c0 + 1) * (HH * WW)]);
            float x2 = __ldg(&x[cbase + (long)(c0 + 2) * (HH * WW)]);
            float x3 = __ldg(&x[cbase + (long)(c0 + 3) * (HH * WW)]);
            float4 r = rr[f4];
            orow[f4] = make_float4(x0 - r.x, x1 - r.y, x2 - r.z, x3 - r.w);
        }
    }

    // ---- fused loss finalize: last CTA (fixed-order, FROZEN) ----
    __threadfence();
    __syncthreads();
    if (tid == 0) {
        int old = atomicAdd(&g_done, 1);
        *Slast = (old == (int)gridDim.x - 1) ? 1 : 0;
    }
    __syncthreads();
    if (*Slast) {
        if (out_size >= LOSS_OFF + QN && tid < 128) {
            int q = tid >> 5, ln = tid & 31;
            float s = 0.f;
            for (int i = ln; i < NCTA; i += 32) s += g_loss_part[i][q];
            #pragma unroll
            for (int off = 16; off; off >>= 1)
                s += __shfl_xor_sync(0xffffffffu, s, off);
            if (ln == 0) out[LOSS_OFF + q] = s / (float)(NROWS * DDIM);
        }
        if (tid == 0) g_done = 0;
    }
}

extern "C" void kernel_launch(void* const* d_in, const int* in_sizes, int n_in,
                              void* d_out, int out_size) {
    const float* x  = (const float*)d_in[0];
    const float* cb = (const float*)d_in[1];
    float* out = (float*)d_out;

    cudaFuncSetAttribute(rvq_main_kernel,
                         cudaFuncAttributeMaxDynamicSharedMemorySize, (int)SMEM_BYTES);

    rvq_prep_kernel<<<(QN*KCODES*32 + 255)/256, 256>>>(cb);
    rvq_main_kernel<<<NCTA, NTHR, SMEM_BYTES>>>(x, cb, out, out_size);
}